// round 1
// baseline (speedup 1.0000x reference)
#include <cuda_runtime.h>

#define NPTS (96*96*96)   // 884736
#define HID 64
#define PPT 4             // points per thread
#define TPB 256

// tanh(x) = 1 - 2/(exp(2x)+1); exact at +/-inf, ~1e-6 rel err via ex2/rcp approx.
__device__ __forceinline__ float fast_tanh(float x) {
    float e = __expf(2.0f * x);
    return 1.0f - __fdividef(2.0f, e + 1.0f);
}

__global__ void __launch_bounds__(TPB)
diffeo_kernel(const float* __restrict__ coords,
              const float* __restrict__ W1_0, const float* __restrict__ b1_0,
              const float* __restrict__ W2_0, const float* __restrict__ b2_0,
              const float* __restrict__ W1_1, const float* __restrict__ b1_1,
              const float* __restrict__ W2_1, const float* __restrict__ b2_1,
              const float* __restrict__ img,
              float* __restrict__ out)
{
    __shared__ float sW1[2][3 * HID];   // [i*64+h]
    __shared__ float sb1[2][HID];
    __shared__ float sW2[2][HID * 3];   // [h*3+j]
    __shared__ float sb2[2][4];

    const int tid = threadIdx.x;
    for (int i = tid; i < 3 * HID; i += TPB) {
        sW1[0][i] = W1_0[i]; sW1[1][i] = W1_1[i];
        sW2[0][i] = W2_0[i]; sW2[1][i] = W2_1[i];
    }
    if (tid < HID) { sb1[0][tid] = b1_0[tid]; sb1[1][tid] = b1_1[tid]; }
    if (tid < 3)   { sb2[0][tid] = b2_0[tid]; sb2[1][tid] = b2_1[tid]; }
    __syncthreads();

    const int base = (blockIdx.x * TPB + tid) * PPT;

    // Load 4 points (12 contiguous floats) as 3x float4
    float y[PPT][3];
    {
        const float4* c4 = reinterpret_cast<const float4*>(coords + (size_t)base * 3);
        float4 q0 = c4[0], q1 = c4[1], q2 = c4[2];
        y[0][0] = q0.x; y[0][1] = q0.y; y[0][2] = q0.z;
        y[1][0] = q0.w; y[1][1] = q1.x; y[1][2] = q1.y;
        y[2][0] = q1.z; y[2][1] = q1.w; y[2][2] = q2.x;
        y[3][0] = q2.y; y[3][1] = q2.z; y[3][2] = q2.w;
    }

    const float h = 0.05f;
    const float wacc[4]  = { h / 6.0f, h / 3.0f, h / 3.0f, h / 6.0f };
    const float wnext[4] = { h * 0.5f, h * 0.5f, h, 0.0f };

    #pragma unroll 1
    for (int ode = 0; ode < 2; ++ode) {
        const float* pW1 = sW1[ode];
        const float* pb1 = sb1[ode];
        const float* pW2 = sW2[ode];
        const float bo0 = sb2[ode][0], bo1 = sb2[ode][1], bo2 = sb2[ode][2];

        #pragma unroll 1
        for (int step = 0; step < 4; ++step) {
            float acc[PPT][3], yt[PPT][3];
            #pragma unroll
            for (int p = 0; p < PPT; ++p)
                #pragma unroll
                for (int j = 0; j < 3; ++j) { acc[p][j] = y[p][j]; yt[p][j] = y[p][j]; }

            #pragma unroll 1
            for (int s = 0; s < 4; ++s) {
                float k[PPT][3];
                #pragma unroll
                for (int p = 0; p < PPT; ++p) { k[p][0] = bo0; k[p][1] = bo1; k[p][2] = bo2; }

                #pragma unroll 4
                for (int hh = 0; hh < HID; ++hh) {
                    float w0 = pW1[hh], w1 = pW1[HID + hh], w2 = pW1[2 * HID + hh];
                    float bb = pb1[hh];
                    float v0 = pW2[hh * 3 + 0], v1 = pW2[hh * 3 + 1], v2 = pW2[hh * 3 + 2];
                    #pragma unroll
                    for (int p = 0; p < PPT; ++p) {
                        float u = fmaf(yt[p][2], w2,
                                  fmaf(yt[p][1], w1,
                                  fmaf(yt[p][0], w0, bb)));
                        float t = fast_tanh(u);
                        k[p][0] = fmaf(t, v0, k[p][0]);
                        k[p][1] = fmaf(t, v1, k[p][1]);
                        k[p][2] = fmaf(t, v2, k[p][2]);
                    }
                }

                const float wa = wacc[s], wn = wnext[s];
                #pragma unroll
                for (int p = 0; p < PPT; ++p)
                    #pragma unroll
                    for (int j = 0; j < 3; ++j) {
                        acc[p][j] = fmaf(wa, k[p][j], acc[p][j]);
                        yt[p][j]  = fmaf(wn, k[p][j], y[p][j]);
                    }
            }

            #pragma unroll
            for (int p = 0; p < PPT; ++p)
                #pragma unroll
                for (int j = 0; j < 3; ++j) y[p][j] = acc[p][j];
        }
    }

    // Trilinear grid sample of img (128^3), padding_mode=zeros, align_corners=False
    // x <- c[...,2], y <- c[...,1], z <- c[...,0]; coord map: ((c+1)*128-1)*0.5 = 64c + 63.5
    #pragma unroll
    for (int p = 0; p < PPT; ++p) {
        float xx = fmaf(y[p][2], 64.0f, 63.5f);
        float yy = fmaf(y[p][1], 64.0f, 63.5f);
        float zz = fmaf(y[p][0], 64.0f, 63.5f);
        float xf = floorf(xx), yf = floorf(yy), zf = floorf(zz);
        float tx = xx - xf, ty = yy - yf, tz = zz - zf;
        int x0 = (int)xf, y0i = (int)yf, z0 = (int)zf;

        float sacc = 0.0f;
        #pragma unroll
        for (int dz = 0; dz < 2; ++dz) {
            float wz = dz ? tz : (1.0f - tz);
            int zi = z0 + dz;
            #pragma unroll
            for (int dy = 0; dy < 2; ++dy) {
                float wy = dy ? ty : (1.0f - ty);
                int yi = y0i + dy;
                #pragma unroll
                for (int dx = 0; dx < 2; ++dx) {
                    float wx = dx ? tx : (1.0f - tx);
                    int xi = x0 + dx;
                    if ((unsigned)xi < 128u && (unsigned)yi < 128u && (unsigned)zi < 128u) {
                        float v = __ldg(&img[((size_t)zi * 128 + yi) * 128 + xi]);
                        sacc = fmaf(v, wz * wy * wx, sacc);
                    }
                }
            }
        }
        out[base + p] = (sacc - 0.5f) * 2.0f;
    }

    // Write c1 (concatenated after reg_out), 12 floats as 3x float4
    {
        float* outc = out + NPTS;
        float4* o4 = reinterpret_cast<float4*>(outc + (size_t)base * 3);
        o4[0] = make_float4(y[0][0], y[0][1], y[0][2], y[1][0]);
        o4[1] = make_float4(y[1][1], y[1][2], y[2][0], y[2][1]);
        o4[2] = make_float4(y[2][2], y[3][0], y[3][1], y[3][2]);
    }
}

extern "C" void kernel_launch(void* const* d_in, const int* in_sizes, int n_in,
                              void* d_out, int out_size)
{
    const float* coords = (const float*)d_in[0];
    const float* W1_0   = (const float*)d_in[1];
    const float* b1_0   = (const float*)d_in[2];
    const float* W2_0   = (const float*)d_in[3];
    const float* b2_0   = (const float*)d_in[4];
    const float* W1_1   = (const float*)d_in[5];
    const float* b1_1   = (const float*)d_in[6];
    const float* W2_1   = (const float*)d_in[7];
    const float* b2_1   = (const float*)d_in[8];
    const float* img    = (const float*)d_in[9];
    float* out = (float*)d_out;

    const int nblocks = NPTS / (TPB * PPT);  // 864
    diffeo_kernel<<<nblocks, TPB>>>(coords,
                                    W1_0, b1_0, W2_0, b2_0,
                                    W1_1, b1_1, W2_1, b2_1,
                                    img, out);
}